// round 2
// baseline (speedup 1.0000x reference)
#include <cuda_runtime.h>
#include <cstdint>

#define SEQ 2048
#define NB 64
#define NF 16
#define HD 512
#define SLOT_PAD 516   // row stride 2064B: fh-lanes land 16B apart mod 128B -> conflict-free LDS.128

// Scratch (allocation-free rule: __device__ globals)
__device__ int g_list[NB * SEQ];   // packed: token_pos | (seg << 16), compacted per batch
__device__ int g_cnt[NB];

__device__ __forceinline__ unsigned long long ffma2(unsigned long long a,
                                                    unsigned long long b,
                                                    unsigned long long c) {
    unsigned long long d;
    asm("fma.rn.f32x2 %0, %1, %2, %3;" : "=l"(d) : "l"(a), "l"(b), "l"(c));
    return d;
}

// ---------------------------------------------------------------------------
// Block-wide exclusive scan over 256 threads (caller syncs between uses)
// ---------------------------------------------------------------------------
__device__ __forceinline__ int block_exscan(int v, int* sh) {
    int lane = threadIdx.x & 31;
    int w = threadIdx.x >> 5;
    int incl = v;
#pragma unroll
    for (int o = 1; o < 32; o <<= 1) {
        int n = __shfl_up_sync(0xFFFFFFFFu, incl, o);
        if (lane >= o) incl += n;
    }
    if (lane == 31) sh[w] = incl;
    __syncthreads();
    if (threadIdx.x < 8) {
        int x = sh[threadIdx.x];
#pragma unroll
        for (int o = 1; o < 8; o <<= 1) {
            int n = __shfl_up_sync(0xFFu, x, o);
            if (threadIdx.x >= (unsigned)o) x += n;
        }
        sh[threadIdx.x] = x;
    }
    __syncthreads();
    int wofs = (w == 0) ? 0 : sh[w - 1];
    return wofs + incl - v;
}

// ---------------------------------------------------------------------------
// Kernel 1 (fused): zero the output (grid-stride float4) + per-batch span ids
// (cumsum of isB - 1) + deterministic compaction of valid tokens.
// One block per batch row, 256 threads x 8 tokens each.
// ---------------------------------------------------------------------------
__global__ __launch_bounds__(256) void seg_zero_kernel(const int* __restrict__ labels,
                                                       const int* pB, const int* pI,
                                                       const int* pMS,
                                                       float* __restrict__ out,
                                                       int out_n) {
    // ---- zeroing part (all blocks participate, overlaps with scan work) ----
    {
        int tid = blockIdx.x * 256 + threadIdx.x;
        int nthreads = gridDim.x * 256;
        int n4 = out_n >> 2;
        float4 z = make_float4(0.f, 0.f, 0.f, 0.f);
        for (int i = tid; i < n4; i += nthreads)
            reinterpret_cast<float4*>(out)[i] = z;
        for (int i = (n4 << 2) + tid; i < out_n; i += nthreads)
            out[i] = 0.0f;
    }

    // ---- segment scan + compaction ----
    __shared__ int sh[8];
    int b = blockIdx.x;
    int t = threadIdx.x;
    int Bv = pB ? *pB : 1;
    int Iv = pI ? *pI : 2;
    int MS = pMS ? *pMS : 512;

    const int4* row = reinterpret_cast<const int4*>(labels + b * SEQ) + t * 2;
    int4 a = row[0];
    int4 c = row[1];
    int lab[8] = {a.x, a.y, a.z, a.w, c.x, c.y, c.z, c.w};

    int incl[8];
    int csum = 0;
#pragma unroll
    for (int i = 0; i < 8; i++) {
        csum += (lab[i] == Bv);
        incl[i] = csum;
    }
    int ex = block_exscan(csum, sh);

    int seg[8], vfl[8];
    int vtot = 0;
#pragma unroll
    for (int i = 0; i < 8; i++) {
        seg[i] = ex + incl[i] - 1;
        vfl[i] = ((lab[i] == Bv) || (lab[i] == Iv)) && seg[i] >= 0 && seg[i] < MS;
        vtot += vfl[i];
    }
    __syncthreads();  // sh reuse barrier
    int vex = block_exscan(vtot, sh);

    int pos = vex;
#pragma unroll
    for (int i = 0; i < 8; i++) {
        if (vfl[i]) {
            g_list[b * SEQ + pos] = (t * 8 + i) | (seg[i] << 16);
            pos++;
        }
    }
    if (t == 255) g_cnt[b] = vex + vtot;
}

// ---------------------------------------------------------------------------
// Kernel 2: for each valid token, project its hidden row (512 f32) onto the
// 16 slot embeddings and atomically scatter into out[b, seg, f].
//
// Layout: 256 threads = 8 warps, 16 tokens/warp, 128 tokens/block.
//   lane = g*8 + fh : g in 0..3 token group (4 tokens each), fh in 0..7.
//   Lane owns f = {fh, fh+8} for its group's 4 tokens -> 8 f32x2 accumulators
//   ((even-d, odd-d) partials so ulonglong2 loads feed fma.rn.f32x2 directly).
// Hidden-row loads are software-prefetched one 4-d chunk ahead so the LDGs
// for chunk d+4 are in flight while the FFMA2s for chunk d issue.
// slot_embs staged transposed in smem: sh[f][d], row pad 516 (conflict-free).
// ---------------------------------------------------------------------------
__global__ __launch_bounds__(256) void proj_kernel(const float* __restrict__ hidden,
                                                   const float* __restrict__ slot,
                                                   const int* pMS,
                                                   float* __restrict__ out) {
    int b = blockIdx.y;
    int cnt = g_cnt[b];
    int tok0 = blockIdx.x * 128;
    if (tok0 >= cnt) return;
    int MS = pMS ? *pMS : 512;

    __shared__ float sh[NF * SLOT_PAD];
    for (int i = threadIdx.x; i < HD * NF; i += 256) {
        int d = i >> 4;
        int f = i & 15;
        sh[f * SLOT_PAD + d] = slot[i];
    }
    __syncthreads();

    int w = threadIdx.x >> 5;
    int lane = threadIdx.x & 31;
    int g = lane >> 3;
    int fh = lane & 7;
    int tbase = tok0 + w * 16 + g * 4;

    const float* base = hidden + (size_t)b * SEQ * HD;
    const float* rows[4];
    int segs[4];
    bool val[4];
#pragma unroll
    for (int j = 0; j < 4; j++) {
        int ti = tbase + j;
        bool v = ti < cnt;
        int p = v ? g_list[b * SEQ + ti] : 0;
        int s = p & 0xFFFF;
        segs[j] = p >> 16;
        rows[j] = base + (size_t)s * HD;
        val[j] = v;
    }

    const float* sp0 = sh + fh * SLOT_PAD;
    const float* sp1 = sh + (fh + 8) * SLOT_PAD;

    unsigned long long acc[4][2];
#pragma unroll
    for (int j = 0; j < 4; j++) {
        acc[j][0] = 0ull;
        acc[j][1] = 0ull;
    }

    // software pipeline: h for chunk d is loaded one iteration ahead
    ulonglong2 hc[4];
#pragma unroll
    for (int j = 0; j < 4; j++)
        hc[j] = *reinterpret_cast<const ulonglong2*>(rows[j]);

#pragma unroll 4
    for (int d = 0; d < HD; d += 4) {
        ulonglong2 hn[4];
        int dn = (d + 4 < HD) ? d + 4 : d;  // last iter reloads (hot in L1), discarded
#pragma unroll
        for (int j = 0; j < 4; j++)
            hn[j] = *reinterpret_cast<const ulonglong2*>(rows[j] + dn);

        ulonglong2 s0 = *reinterpret_cast<const ulonglong2*>(sp0 + d);
        ulonglong2 s1 = *reinterpret_cast<const ulonglong2*>(sp1 + d);
#pragma unroll
        for (int j = 0; j < 4; j++) {
            acc[j][0] = ffma2(hc[j].x, s0.x, acc[j][0]);
            acc[j][0] = ffma2(hc[j].y, s0.y, acc[j][0]);
            acc[j][1] = ffma2(hc[j].x, s1.x, acc[j][1]);
            acc[j][1] = ffma2(hc[j].y, s1.y, acc[j][1]);
        }
#pragma unroll
        for (int j = 0; j < 4; j++)
            hc[j] = hn[j];
    }

#pragma unroll
    for (int j = 0; j < 4; j++) {
        if (!val[j]) continue;
        float* op = out + ((size_t)b * MS + segs[j]) * NF;
        float2 v0 = *reinterpret_cast<float2*>(&acc[j][0]);
        float2 v1 = *reinterpret_cast<float2*>(&acc[j][1]);
        atomicAdd(op + fh, v0.x + v0.y);
        atomicAdd(op + fh + 8, v1.x + v1.y);
    }
}

// ---------------------------------------------------------------------------
extern "C" void kernel_launch(void* const* d_in, const int* in_sizes, int n_in,
                              void* d_out, int out_size) {
    const float* hidden = (const float*)d_in[0];
    const float* slot = (const float*)d_in[1];
    const int* labels = (const int*)d_in[2];
    const int* pB = (n_in > 3) ? (const int*)d_in[3] : nullptr;
    const int* pI = (n_in > 4) ? (const int*)d_in[4] : nullptr;
    const int* pMS = (n_in > 5) ? (const int*)d_in[5] : nullptr;
    float* out = (float*)d_out;

    seg_zero_kernel<<<NB, 256>>>(labels, pB, pI, pMS, out, out_size);
    proj_kernel<<<dim3(16, NB), 256>>>(hidden, slot, pMS, out);
}

// round 3
// speedup vs baseline: 1.3237x; 1.3237x over previous
#include <cuda_runtime.h>
#include <cstdint>

#define SEQ 2048
#define NB 64
#define NF 16
#define HD 512
#define SLOT_PAD 516            // floats per f-row in smem (2064B, 16B-aligned, conflict-free)
#define T_TILE 64               // tokens per block tile
#define ROWB 528                // bytes per staged token row (512 + 16 pad; 528/16=33 odd -> uniform banks)
#define STAGE_BYTES (T_TILE * ROWB)      // 33792
#define SLOT_BYTES (NF * SLOT_PAD * 4)   // 33024
#define SMEM_TOTAL (SLOT_BYTES + 4 * STAGE_BYTES)  // 168192

// Scratch (allocation-free rule: __device__ globals)
__device__ int g_list[NB * SEQ];   // packed: token_pos | (seg << 16), compacted per batch
__device__ int g_cnt[NB];

__device__ __forceinline__ unsigned long long ffma2(unsigned long long a,
                                                    unsigned long long b,
                                                    unsigned long long c) {
    unsigned long long d;
    asm("fma.rn.f32x2 %0, %1, %2, %3;" : "=l"(d) : "l"(a), "l"(b), "l"(c));
    return d;
}

__device__ __forceinline__ void cp16(void* dst_smem, const void* src) {
    unsigned saddr = (unsigned)__cvta_generic_to_shared(dst_smem);
    asm volatile("cp.async.cg.shared.global [%0], [%1], 16;" :: "r"(saddr), "l"(src));
}
__device__ __forceinline__ void cp_commit() {
    asm volatile("cp.async.commit_group;");
}
template <int N>
__device__ __forceinline__ void cp_wait() {
    asm volatile("cp.async.wait_group %0;" :: "n"(N));
}

// ---------------------------------------------------------------------------
// Block-wide exclusive scan over 256 threads (caller syncs between uses)
// ---------------------------------------------------------------------------
__device__ __forceinline__ int block_exscan(int v, int* sh) {
    int lane = threadIdx.x & 31;
    int w = threadIdx.x >> 5;
    int incl = v;
#pragma unroll
    for (int o = 1; o < 32; o <<= 1) {
        int n = __shfl_up_sync(0xFFFFFFFFu, incl, o);
        if (lane >= o) incl += n;
    }
    if (lane == 31) sh[w] = incl;
    __syncthreads();
    if (threadIdx.x < 8) {
        int x = sh[threadIdx.x];
#pragma unroll
        for (int o = 1; o < 8; o <<= 1) {
            int n = __shfl_up_sync(0xFFu, x, o);
            if (threadIdx.x >= (unsigned)o) x += n;
        }
        sh[threadIdx.x] = x;
    }
    __syncthreads();
    int wofs = (w == 0) ? 0 : sh[w - 1];
    return wofs + incl - v;
}

// ---------------------------------------------------------------------------
// Kernel 1 (fused): zero output + per-batch span ids + compaction.
// ---------------------------------------------------------------------------
__global__ __launch_bounds__(256) void seg_zero_kernel(const int* __restrict__ labels,
                                                       const int* pB, const int* pI,
                                                       const int* pMS,
                                                       float* __restrict__ out,
                                                       int out_n) {
    {
        int tid = blockIdx.x * 256 + threadIdx.x;
        int nthreads = gridDim.x * 256;
        int n4 = out_n >> 2;
        float4 z = make_float4(0.f, 0.f, 0.f, 0.f);
        for (int i = tid; i < n4; i += nthreads)
            reinterpret_cast<float4*>(out)[i] = z;
        for (int i = (n4 << 2) + tid; i < out_n; i += nthreads)
            out[i] = 0.0f;
    }

    __shared__ int sh[8];
    int b = blockIdx.x;
    int t = threadIdx.x;
    int Bv = pB ? *pB : 1;
    int Iv = pI ? *pI : 2;
    int MS = pMS ? *pMS : 512;

    const int4* row = reinterpret_cast<const int4*>(labels + b * SEQ) + t * 2;
    int4 a = row[0];
    int4 c = row[1];
    int lab[8] = {a.x, a.y, a.z, a.w, c.x, c.y, c.z, c.w};

    int incl[8];
    int csum = 0;
#pragma unroll
    for (int i = 0; i < 8; i++) {
        csum += (lab[i] == Bv);
        incl[i] = csum;
    }
    int ex = block_exscan(csum, sh);

    int seg[8], vfl[8];
    int vtot = 0;
#pragma unroll
    for (int i = 0; i < 8; i++) {
        seg[i] = ex + incl[i] - 1;
        vfl[i] = ((lab[i] == Bv) || (lab[i] == Iv)) && seg[i] >= 0 && seg[i] < MS;
        vtot += vfl[i];
    }
    __syncthreads();
    int vex = block_exscan(vtot, sh);

    int pos = vex;
#pragma unroll
    for (int i = 0; i < 8; i++) {
        if (vfl[i]) {
            g_list[b * SEQ + pos] = (t * 8 + i) | (seg[i] << 16);
            pos++;
        }
    }
    if (t == 255) g_cnt[b] = vex + vtot;
}

// ---------------------------------------------------------------------------
// Kernel 2: cp.async-staged gather-projection.
//
// Block handles 64 tokens. The 64 x 2KB tile is staged into smem as 4 stages
// of 128 d-floats (33KB each), ALL issued up-front via cp.async (32 LDGSTS /
// thread -> ~128KB in flight). Compute consumes stage s after wait_group<3-s>.
//
// Staging addressing: thread t -> token tt=t/4, quarter q=t%3..0. Within a
// stage, thread covers bytes q*16 + i*64 (i=0..7) of the token's 512B segment,
// identical offsets in gmem and smem (linear layout, uniform banks: row
// stride 528B => bank group = (33*tok + chunk) % 8).
//
// Compute: 8 warps x 8 tokens (4 groups x 2). lane = g*8+fh owns its group's
// 2 tokens x f={fh, fh+8}; f32x2 accumulators over all 4 stages, then one
// atomicAdd per (token, f) into out[b, seg, f].
// ---------------------------------------------------------------------------
__global__ __launch_bounds__(256, 1) void proj_kernel(const float* __restrict__ hidden,
                                                      const float* __restrict__ slot,
                                                      const int* pMS,
                                                      float* __restrict__ out) {
    int b = blockIdx.y;
    int cnt = g_cnt[b];
    int tbase = blockIdx.x * T_TILE;
    if (tbase >= cnt) return;
    int MS = pMS ? *pMS : 512;

    extern __shared__ float smem[];
    float* slot_sh = smem;                               // NF * SLOT_PAD floats
    char* ring = reinterpret_cast<char*>(smem) + SLOT_BYTES;  // 4 * STAGE_BYTES

    // ---- gather addressing (per thread) ----
    int tt = threadIdx.x >> 2;       // token slot in tile: 0..63
    int q = threadIdx.x & 3;         // quarter: 0..3
    int gidx = tbase + tt;
    int cidx = gidx < cnt ? gidx : cnt - 1;  // clamp (masked at scatter)
    int packed_g = g_list[b * SEQ + cidx];
    const float* grow = hidden + (size_t)b * SEQ * HD + (size_t)(packed_g & 0xFFFF) * HD;

    // ---- issue all 4 stages up-front ----
#pragma unroll
    for (int s = 0; s < 4; s++) {
        const float* src = grow + s * 128 + q * 4;               // +i*16 floats
        char* dst = ring + s * STAGE_BYTES + tt * ROWB + q * 16;  // +i*64 bytes
#pragma unroll
        for (int i = 0; i < 8; i++)
            cp16(dst + i * 64, src + i * 16);
        cp_commit();
    }

    // ---- stage slot_embs transposed while loads fly ----
    for (int i = threadIdx.x; i < HD * NF; i += 256) {
        int d = i >> 4;
        int f = i & 15;
        slot_sh[f * SLOT_PAD + d] = slot[i];
    }

    // ---- compute-side setup ----
    int w = threadIdx.x >> 5;
    int lane = threadIdx.x & 31;
    int g = lane >> 3;
    int fh = lane & 7;
    int tokA = w * 8 + g * 2;        // tile-local
    int tokB = tokA + 1;

    const float* sp0 = slot_sh + fh * SLOT_PAD;
    const float* sp1 = slot_sh + (fh + 8) * SLOT_PAD;

    unsigned long long a00 = 0, a01 = 0, a10 = 0, a11 = 0;

    auto compute_stage = [&](int s) {
        const char* stA = ring + s * STAGE_BYTES + tokA * ROWB;
        const float* sl0 = sp0 + s * 128;
        const float* sl1 = sp1 + s * 128;
#pragma unroll 4
        for (int c = 0; c < 32; c++) {
            ulonglong2 S0 = *reinterpret_cast<const ulonglong2*>(sl0 + c * 4);
            ulonglong2 S1 = *reinterpret_cast<const ulonglong2*>(sl1 + c * 4);
            ulonglong2 HA = *reinterpret_cast<const ulonglong2*>(stA + c * 16);
            ulonglong2 HB = *reinterpret_cast<const ulonglong2*>(stA + ROWB + c * 16);
            a00 = ffma2(HA.x, S0.x, a00);
            a00 = ffma2(HA.y, S0.y, a00);
            a01 = ffma2(HA.x, S1.x, a01);
            a01 = ffma2(HA.y, S1.y, a01);
            a10 = ffma2(HB.x, S0.x, a10);
            a10 = ffma2(HB.y, S0.y, a10);
            a11 = ffma2(HB.x, S1.x, a11);
            a11 = ffma2(HB.y, S1.y, a11);
        }
    };

    cp_wait<3>();
    __syncthreads();   // also covers slot_sh stores
    compute_stage(0);
    cp_wait<2>();
    __syncthreads();
    compute_stage(1);
    cp_wait<1>();
    __syncthreads();
    compute_stage(2);
    cp_wait<0>();
    __syncthreads();
    compute_stage(3);

    // ---- scatter ----
    int giA = tbase + tokA;
    int giB = tbase + tokB;
    if (giA < cnt) {
        int p = g_list[b * SEQ + giA];
        float* op = out + ((size_t)b * MS + (p >> 16)) * NF;
        float2 v0 = *reinterpret_cast<float2*>(&a00);
        float2 v1 = *reinterpret_cast<float2*>(&a01);
        atomicAdd(op + fh, v0.x + v0.y);
        atomicAdd(op + fh + 8, v1.x + v1.y);
    }
    if (giB < cnt) {
        int p = g_list[b * SEQ + giB];
        float* op = out + ((size_t)b * MS + (p >> 16)) * NF;
        float2 v0 = *reinterpret_cast<float2*>(&a10);
        float2 v1 = *reinterpret_cast<float2*>(&a11);
        atomicAdd(op + fh, v0.x + v0.y);
        atomicAdd(op + fh + 8, v1.x + v1.y);
    }
}

// ---------------------------------------------------------------------------
extern "C" void kernel_launch(void* const* d_in, const int* in_sizes, int n_in,
                              void* d_out, int out_size) {
    const float* hidden = (const float*)d_in[0];
    const float* slot = (const float*)d_in[1];
    const int* labels = (const int*)d_in[2];
    const int* pB = (n_in > 3) ? (const int*)d_in[3] : nullptr;
    const int* pI = (n_in > 4) ? (const int*)d_in[4] : nullptr;
    const int* pMS = (n_in > 5) ? (const int*)d_in[5] : nullptr;
    float* out = (float*)d_out;

    static bool attr_set = false;
    if (!attr_set) {
        cudaFuncSetAttribute(proj_kernel, cudaFuncAttributeMaxDynamicSharedMemorySize,
                             SMEM_TOTAL);
        attr_set = true;
    }

    seg_zero_kernel<<<NB, 256>>>(labels, pB, pI, pMS, out, out_size);
    proj_kernel<<<dim3(SEQ / T_TILE, NB), 256, SMEM_TOTAL>>>(hidden, slot, pMS, out);
}

// round 4
// speedup vs baseline: 1.5934x; 1.2037x over previous
#include <cuda_runtime.h>
#include <cstdint>

#define SEQ 2048
#define NB 64
#define NF 16
#define HD 512
#define SLOT_PAD 516                 // 129*16B rows: conflict-free S reads
#define SLOT_BYTES (NF * SLOT_PAD * 4)   // 33024
#define U_TOK 64                     // tokens per unit
#define STAGE_B 8192                 // 8 c-chunks * 64 slots * 16B
#define WARP_RING (2 * STAGE_B)      // double buffer per warp
#define NW 4                         // warps per block (each owns a 128-d quarter)
#define SMEM_TOTAL (SLOT_BYTES + NW * WARP_RING)  // 98560 -> 2 blocks/SM
#define GRID_X 512
#define N_UNITS (32 * NB)            // 32 x-slots * 64 batches (x-major: u = x*64+b)

// Scratch (allocation-free rule: __device__ globals)
__device__ int g_list[NB * SEQ];   // packed: token_pos | (seg << 16), compacted per batch
__device__ int g_cnt[NB];

__device__ __forceinline__ unsigned long long ffma2(unsigned long long a,
                                                    unsigned long long b,
                                                    unsigned long long c) {
    unsigned long long d;
    asm("fma.rn.f32x2 %0, %1, %2, %3;" : "=l"(d) : "l"(a), "l"(b), "l"(c));
    return d;
}

__device__ __forceinline__ void cp16(void* dst_smem, const void* src) {
    unsigned saddr = (unsigned)__cvta_generic_to_shared(dst_smem);
    asm volatile("cp.async.cg.shared.global [%0], [%1], 16;" :: "r"(saddr), "l"(src));
}
__device__ __forceinline__ void cp_commit() {
    asm volatile("cp.async.commit_group;");
}
template <int N>
__device__ __forceinline__ void cp_wait() {
    asm volatile("cp.async.wait_group %0;" :: "n"(N));
}

// bank-swizzled slot for token t: distinct banks for consecutive-t (stores)
// and stride-8-t (reads) access groups.
__device__ __forceinline__ int tok_slot(int t) {
    return (t & 0x38) | ((t ^ (t >> 3)) & 7);
}

// ---------------------------------------------------------------------------
// Block-wide exclusive scan over 256 threads
// ---------------------------------------------------------------------------
__device__ __forceinline__ int block_exscan(int v, int* sh) {
    int lane = threadIdx.x & 31;
    int w = threadIdx.x >> 5;
    int incl = v;
#pragma unroll
    for (int o = 1; o < 32; o <<= 1) {
        int n = __shfl_up_sync(0xFFFFFFFFu, incl, o);
        if (lane >= o) incl += n;
    }
    if (lane == 31) sh[w] = incl;
    __syncthreads();
    if (threadIdx.x < 8) {
        int x = sh[threadIdx.x];
#pragma unroll
        for (int o = 1; o < 8; o <<= 1) {
            int n = __shfl_up_sync(0xFFu, x, o);
            if (threadIdx.x >= (unsigned)o) x += n;
        }
        sh[threadIdx.x] = x;
    }
    __syncthreads();
    int wofs = (w == 0) ? 0 : sh[w - 1];
    return wofs + incl - v;
}

// ---------------------------------------------------------------------------
// Kernel 1 (fused): zero output + per-batch span ids + compaction.
// ---------------------------------------------------------------------------
__global__ __launch_bounds__(256) void seg_zero_kernel(const int* __restrict__ labels,
                                                       const int* pB, const int* pI,
                                                       const int* pMS,
                                                       float* __restrict__ out,
                                                       int out_n) {
    {
        int tid = blockIdx.x * 256 + threadIdx.x;
        int nthreads = gridDim.x * 256;
        int n4 = out_n >> 2;
        float4 z = make_float4(0.f, 0.f, 0.f, 0.f);
        for (int i = tid; i < n4; i += nthreads)
            reinterpret_cast<float4*>(out)[i] = z;
        for (int i = (n4 << 2) + tid; i < out_n; i += nthreads)
            out[i] = 0.0f;
    }

    __shared__ int sh[8];
    int b = blockIdx.x;
    int t = threadIdx.x;
    int Bv = pB ? *pB : 1;
    int Iv = pI ? *pI : 2;
    int MS = pMS ? *pMS : 512;

    const int4* row = reinterpret_cast<const int4*>(labels + b * SEQ) + t * 2;
    int4 a = row[0];
    int4 c = row[1];
    int lab[8] = {a.x, a.y, a.z, a.w, c.x, c.y, c.z, c.w};

    int incl[8];
    int csum = 0;
#pragma unroll
    for (int i = 0; i < 8; i++) {
        csum += (lab[i] == Bv);
        incl[i] = csum;
    }
    int ex = block_exscan(csum, sh);

    int seg[8], vfl[8];
    int vtot = 0;
#pragma unroll
    for (int i = 0; i < 8; i++) {
        seg[i] = ex + incl[i] - 1;
        vfl[i] = ((lab[i] == Bv) || (lab[i] == Iv)) && seg[i] >= 0 && seg[i] < MS;
        vtot += vfl[i];
    }
    __syncthreads();
    int vex = block_exscan(vtot, sh);

    int pos = vex;
#pragma unroll
    for (int i = 0; i < 8; i++) {
        if (vfl[i]) {
            g_list[b * SEQ + pos] = (t * 8 + i) | (seg[i] << 16);
            pos++;
        }
    }
    if (t == 255) g_cnt[b] = vex + vtot;
}

// ---------------------------------------------------------------------------
// Kernel 2: warp-autonomous gather-projection.
//
// Unit = 64 compacted tokens of one batch (u = x*64 + b, x-major so working
// units are contiguous). A block's 4 warps each own a 128-d quarter of the
// unit; each warp streams its quarter in 4 cp.async stages (32 d = 8 16B
// chunks x 64 tokens, XOR-swizzled token slots) through a private double
// buffer. Lane (tg, fg) register-tiles 8 tokens x 4 f's: per 16B chunk it
// loads 8 H + 4 S (192 B) for 128 MACs -> 2.7x less crossbar traffic than R3.
// Partial (quarter-d) sums scatter via atomicAdd.
// ---------------------------------------------------------------------------
__global__ __launch_bounds__(128) void proj_kernel(const float* __restrict__ hidden,
                                                   const float* __restrict__ slot,
                                                   const int* pMS,
                                                   float* __restrict__ out) {
    extern __shared__ float smem[];
    float* slot_sh = smem;
    char* ring = reinterpret_cast<char*>(smem) + SLOT_BYTES;
    int MS = pMS ? *pMS : 512;

    // stage slot_embs transposed: slot_sh[f][d]
    for (int i = threadIdx.x; i < HD * NF; i += 128) {
        int d = i >> 4;
        int f = i & 15;
        slot_sh[f * SLOT_PAD + d] = slot[i];
    }
    __syncthreads();

    int w = threadIdx.x >> 5;
    int lane = threadIdx.x & 31;
    int tg = lane >> 2;       // token group 0..7
    int fg = lane & 3;        // f group 0..3
    char* buf0 = ring + w * WARP_RING;
    char* buf1 = buf0 + STAGE_B;

    // loader-side: this lane stages tokens (lane) and (lane+32)
    int slA16 = tok_slot(lane) * 16;
    int slB16 = tok_slot(lane + 32) * 16;

    // compute-side: byte offsets of this lane's 8 tokens' slots
    int cs16[8];
#pragma unroll
    for (int j = 0; j < 8; j++)
        cs16[j] = tok_slot(8 * tg + j) * 16;

    const float* sp[4];
#pragma unroll
    for (int k = 0; k < 4; k++)
        sp[k] = slot_sh + (fg + 4 * k) * SLOT_PAD + w * 128;

    for (int u = blockIdx.x; u < N_UNITS; u += GRID_X) {
        int x = u >> 6;
        int b = u & 63;
        int cnt = g_cnt[b];
        int t0 = x * U_TOK;
        if (t0 >= cnt) continue;
        int m = cnt - t0;
        if (m > U_TOK) m = U_TOK;

        // row pointers for this lane's two staged tokens (clamped; masked later)
        int iA = t0 + (lane < m ? lane : m - 1);
        int iB = t0 + (lane + 32 < m ? lane + 32 : m - 1);
        const float* base = hidden + (size_t)b * SEQ * HD + w * 128;
        const float* srcA = base + (size_t)(g_list[b * SEQ + iA] & 0xFFFF) * HD;
        const float* srcB = base + (size_t)(g_list[b * SEQ + iB] & 0xFFFF) * HD;

        auto issue_stage = [&](int s, char* buf) {
            const float* sa = srcA + s * 32;
            const float* sb = srcB + s * 32;
#pragma unroll
            for (int c = 0; c < 8; c++) {
                cp16(buf + c * 1024 + slA16, sa + c * 4);
                cp16(buf + c * 1024 + slB16, sb + c * 4);
            }
            cp_commit();
        };

        unsigned long long acc[8][4];
#pragma unroll
        for (int j = 0; j < 8; j++)
#pragma unroll
            for (int k = 0; k < 4; k++) acc[j][k] = 0ull;

        auto compute_stage = [&](int s, const char* buf) {
            int dq = s * 32;
#pragma unroll 2
            for (int c = 0; c < 8; c++) {
                ulonglong2 S[4];
#pragma unroll
                for (int k = 0; k < 4; k++)
                    S[k] = *reinterpret_cast<const ulonglong2*>(sp[k] + dq + c * 4);
#pragma unroll
                for (int j = 0; j < 8; j++) {
                    ulonglong2 H = *reinterpret_cast<const ulonglong2*>(buf + c * 1024 + cs16[j]);
#pragma unroll
                    for (int k = 0; k < 4; k++) {
                        acc[j][k] = ffma2(H.x, S[k].x, acc[j][k]);
                        acc[j][k] = ffma2(H.y, S[k].y, acc[j][k]);
                    }
                }
            }
        };

        issue_stage(0, buf0);
        issue_stage(1, buf1);
        cp_wait<1>();
        __syncwarp();
        compute_stage(0, buf0);
        issue_stage(2, buf0);
        cp_wait<1>();
        __syncwarp();
        compute_stage(1, buf1);
        issue_stage(3, buf1);
        cp_wait<1>();
        __syncwarp();
        compute_stage(2, buf0);
        cp_wait<0>();
        __syncwarp();
        compute_stage(3, buf1);

        // scatter partial (quarter-d) sums
#pragma unroll
        for (int j = 0; j < 8; j++) {
            int ti = 8 * tg + j;
            if (ti >= m) continue;
            int p = g_list[b * SEQ + t0 + ti];
            float* op = out + ((size_t)b * MS + (p >> 16)) * NF;
#pragma unroll
            for (int k = 0; k < 4; k++) {
                float2 v = *reinterpret_cast<float2*>(&acc[j][k]);
                atomicAdd(op + fg + 4 * k, v.x + v.y);
            }
        }
        __syncwarp();  // all lanes done reading bufs before next unit overwrites
    }
}

// ---------------------------------------------------------------------------
extern "C" void kernel_launch(void* const* d_in, const int* in_sizes, int n_in,
                              void* d_out, int out_size) {
    const float* hidden = (const float*)d_in[0];
    const float* slot = (const float*)d_in[1];
    const int* labels = (const int*)d_in[2];
    const int* pB = (n_in > 3) ? (const int*)d_in[3] : nullptr;
    const int* pI = (n_in > 4) ? (const int*)d_in[4] : nullptr;
    const int* pMS = (n_in > 5) ? (const int*)d_in[5] : nullptr;
    float* out = (float*)d_out;

    static bool attr_set = false;
    if (!attr_set) {
        cudaFuncSetAttribute(proj_kernel, cudaFuncAttributeMaxDynamicSharedMemorySize,
                             SMEM_TOTAL);
        attr_set = true;
    }

    seg_zero_kernel<<<NB, 256>>>(labels, pB, pI, pMS, out, out_size);
    proj_kernel<<<GRID_X, 128, SMEM_TOTAL>>>(hidden, slot, pMS, out);
}

// round 5
// speedup vs baseline: 2.2470x; 1.4102x over previous
#include <cuda_runtime.h>
#include <cstdint>

#define SEQ 2048
#define NB 64
#define NF 16
#define HD 512
#define SLOT_PAD 516                     // 129 16B-units/row -> stride ≡1 mod 8: conflict-free
#define SLOT_BYTES (NF * SLOT_PAD * 4)   // 33024
#define U_TOK 64                         // tokens per unit (block)
#define W_TOK 32                         // tokens per warp
#define STAGE_B 4096                     // 32 tok x 32 d x 4B
#define NW 8                             // warps/block: 4 d-quarters x 2 token-halves
#define SMEM_TOTAL (SLOT_BYTES + NW * 2 * STAGE_B)  // 98560 -> 2 blocks/SM
#define N_UNITS ((SEQ / U_TOK) * NB)     // 2048, x-major: u = x*64 + b
#define GRID_X 296                       // 2/SM x 148 SM: single wave

// Scratch (allocation-free rule: __device__ globals)
__device__ int g_list[NB * SEQ];   // packed: token_pos | (seg << 16), compacted per batch
__device__ int g_cnt[NB];

__device__ __forceinline__ unsigned long long ffma2(unsigned long long a,
                                                    unsigned long long b,
                                                    unsigned long long c) {
    unsigned long long d;
    asm("fma.rn.f32x2 %0, %1, %2, %3;" : "=l"(d) : "l"(a), "l"(b), "l"(c));
    return d;
}

__device__ __forceinline__ void cp16(void* dst_smem, const void* src) {
    unsigned saddr = (unsigned)__cvta_generic_to_shared(dst_smem);
    asm volatile("cp.async.cg.shared.global [%0], [%1], 16;" :: "r"(saddr), "l"(src));
}
__device__ __forceinline__ void cp_commit() {
    asm volatile("cp.async.commit_group;");
}
template <int N>
__device__ __forceinline__ void cp_wait() {
    asm volatile("cp.async.wait_group %0;" :: "n"(N));
}

// stage smem swizzle: 16B-unit address for (token t in 0..31, chunk c in 0..7)
__device__ __forceinline__ int sw16(int t, int c) {
    return t * 8 + ((c + t + (t >> 3)) & 7);
}

// ---------------------------------------------------------------------------
// Block-wide exclusive scan over 256 threads
// ---------------------------------------------------------------------------
__device__ __forceinline__ int block_exscan(int v, int* sh) {
    int lane = threadIdx.x & 31;
    int w = threadIdx.x >> 5;
    int incl = v;
#pragma unroll
    for (int o = 1; o < 32; o <<= 1) {
        int n = __shfl_up_sync(0xFFFFFFFFu, incl, o);
        if (lane >= o) incl += n;
    }
    if (lane == 31) sh[w] = incl;
    __syncthreads();
    if (threadIdx.x < 8) {
        int x = sh[threadIdx.x];
#pragma unroll
        for (int o = 1; o < 8; o <<= 1) {
            int n = __shfl_up_sync(0xFFu, x, o);
            if (threadIdx.x >= (unsigned)o) x += n;
        }
        sh[threadIdx.x] = x;
    }
    __syncthreads();
    int wofs = (w == 0) ? 0 : sh[w - 1];
    return wofs + incl - v;
}

// ---------------------------------------------------------------------------
// Kernel 1 (fused): zero output (all 256 blocks) + per-batch span ids +
// compaction (first 64 blocks).
// ---------------------------------------------------------------------------
__global__ __launch_bounds__(256) void seg_zero_kernel(const int* __restrict__ labels,
                                                       const int* pB, const int* pI,
                                                       const int* pMS,
                                                       float* __restrict__ out,
                                                       int out_n) {
    {
        int tid = blockIdx.x * 256 + threadIdx.x;
        int nthreads = gridDim.x * 256;
        int n4 = out_n >> 2;
        float4 z = make_float4(0.f, 0.f, 0.f, 0.f);
        for (int i = tid; i < n4; i += nthreads)
            reinterpret_cast<float4*>(out)[i] = z;
        for (int i = (n4 << 2) + tid; i < out_n; i += nthreads)
            out[i] = 0.0f;
    }
    if (blockIdx.x >= NB) return;

    __shared__ int sh[8];
    int b = blockIdx.x;
    int t = threadIdx.x;
    int Bv = pB ? *pB : 1;
    int Iv = pI ? *pI : 2;
    int MS = pMS ? *pMS : 512;

    const int4* row = reinterpret_cast<const int4*>(labels + b * SEQ) + t * 2;
    int4 a = row[0];
    int4 c = row[1];
    int lab[8] = {a.x, a.y, a.z, a.w, c.x, c.y, c.z, c.w};

    int incl[8];
    int csum = 0;
#pragma unroll
    for (int i = 0; i < 8; i++) {
        csum += (lab[i] == Bv);
        incl[i] = csum;
    }
    int ex = block_exscan(csum, sh);

    int seg[8], vfl[8];
    int vtot = 0;
#pragma unroll
    for (int i = 0; i < 8; i++) {
        seg[i] = ex + incl[i] - 1;
        vfl[i] = ((lab[i] == Bv) || (lab[i] == Iv)) && seg[i] >= 0 && seg[i] < MS;
        vtot += vfl[i];
    }
    __syncthreads();
    int vex = block_exscan(vtot, sh);

    int pos = vex;
#pragma unroll
    for (int i = 0; i < 8; i++) {
        if (vfl[i]) {
            g_list[b * SEQ + pos] = (t * 8 + i) | (seg[i] << 16);
            pos++;
        }
    }
    if (t == 255) g_cnt[b] = vex + vtot;
}

// ---------------------------------------------------------------------------
// Kernel 2: warp-autonomous gather-projection, 16 warps/SM.
//
// Unit = 64 compacted tokens of batch b (u = x*64 + b, x-major). Block = 8
// warps: warp (q = w&3, h = w>>2) owns d-quarter q of tokens [32h, 32h+32).
// Each warp streams its 32tok x 128d slice in 4 cp.async stages of 32 d
// through a private double buffer (4 KB stages).
//
// Staging (coalesced): lane (r4 = l>>2, qq = l&3) covers tokens r4+8m
// (m=0..3), chunks {qq, qq+4} -> each cp16 instr touches 8 rows x <=64B
// (nL~8). Swizzle sw16 gives minimal-wavefront stores AND 1-wavefront reads.
//
// Compute: lane (tg = l>>2, fg = l&3) tiles 4 tokens x 4 f's; per 16B chunk:
// 4 H + 4 S LDS (all broadcast-deduped, conflict-free) feeding 32 FFMA2.
// Quarter-d partial sums scatter via atomicAdd.
// ---------------------------------------------------------------------------
__global__ __launch_bounds__(256, 2) void proj_kernel(const float* __restrict__ hidden,
                                                      const float* __restrict__ slot,
                                                      const int* pMS,
                                                      float* __restrict__ out) {
    extern __shared__ float smem[];
    float* slot_sh = smem;
    char* ring = reinterpret_cast<char*>(smem) + SLOT_BYTES;
    int MS = pMS ? *pMS : 512;

    // stage slot_embs transposed: slot_sh[f][d]
    for (int i = threadIdx.x; i < HD * NF; i += 256) {
        int d = i >> 4;
        int f = i & 15;
        slot_sh[f * SLOT_PAD + d] = slot[i];
    }
    __syncthreads();

    int w = threadIdx.x >> 5;
    int lane = threadIdx.x & 31;
    int q = w & 3;            // d-quarter
    int h = w >> 2;           // token half
    char* buf0 = ring + w * 2 * STAGE_B;
    char* buf1 = buf0 + STAGE_B;

    int r4 = lane >> 2;       // staging: row group / compute: token group (0..7)
    int qq = lane & 3;        // staging: chunk quad / compute: f group (0..3)

    // staging smem byte-offsets (unit-invariant): tokens r4+8m, chunks qq, qq+4
    int dst16[4][2];
#pragma unroll
    for (int m = 0; m < 4; m++) {
        dst16[m][0] = sw16(r4 + 8 * m, qq) * 16;
        dst16[m][1] = sw16(r4 + 8 * m, qq + 4) * 16;
    }

    const float* sp[4];
#pragma unroll
    for (int k = 0; k < 4; k++)
        sp[k] = slot_sh + (qq + 4 * k) * SLOT_PAD + q * 128;

    for (int u = blockIdx.x; u < N_UNITS; u += GRID_X) {
        int x = u >> 6;
        int b = u & 63;
        int cnt = g_cnt[b];
        if (x * U_TOK >= cnt) continue;     // uniform across block
        int t0 = x * U_TOK + h * W_TOK;     // this warp's first compacted token

        // row pointers for staging (clamped; masked at scatter)
        const float* base = hidden + (size_t)b * SEQ * HD + q * 128;
        const float* rowp[4];
#pragma unroll
        for (int m = 0; m < 4; m++) {
            int ti = t0 + r4 + 8 * m;
            if (ti >= cnt) ti = cnt - 1;
            rowp[m] = base + (size_t)(g_list[b * SEQ + ti] & 0xFFFF) * HD;
        }

        auto issue = [&](int s, char* buf) {
#pragma unroll
            for (int m = 0; m < 4; m++) {
                const float* src = rowp[m] + s * 32;
                cp16(buf + dst16[m][0], src + qq * 4);
                cp16(buf + dst16[m][1], src + (qq + 4) * 4);
            }
            cp_commit();
        };

        unsigned long long acc[4][4];
#pragma unroll
        for (int j = 0; j < 4; j++)
#pragma unroll
            for (int k = 0; k < 4; k++) acc[j][k] = 0ull;

        auto comp = [&](int s, const char* buf) {
#pragma unroll
            for (int c = 0; c < 8; c++) {
                ulonglong2 S[4];
#pragma unroll
                for (int k = 0; k < 4; k++)
                    S[k] = *reinterpret_cast<const ulonglong2*>(sp[k] + s * 32 + c * 4);
#pragma unroll
                for (int j = 0; j < 4; j++) {
                    int t = 4 * r4 + j;
                    ulonglong2 H = *reinterpret_cast<const ulonglong2*>(buf + sw16(t, c) * 16);
#pragma unroll
                    for (int k = 0; k < 4; k++) {
                        acc[j][k] = ffma2(H.x, S[k].x, acc[j][k]);
                        acc[j][k] = ffma2(H.y, S[k].y, acc[j][k]);
                    }
                }
            }
        };

        issue(0, buf0);
        issue(1, buf1);
        cp_wait<1>();
        __syncwarp();
        comp(0, buf0);
        issue(2, buf0);
        cp_wait<1>();
        __syncwarp();
        comp(1, buf1);
        issue(3, buf1);
        cp_wait<1>();
        __syncwarp();
        comp(2, buf0);
        cp_wait<0>();
        __syncwarp();
        comp(3, buf1);

        // scatter quarter-d partial sums
#pragma unroll
        for (int j = 0; j < 4; j++) {
            int ti = t0 + 4 * r4 + j;
            if (ti >= cnt) continue;
            int p = g_list[b * SEQ + ti];
            float* op = out + ((size_t)b * MS + (p >> 16)) * NF;
#pragma unroll
            for (int k = 0; k < 4; k++) {
                float2 v = *reinterpret_cast<float2*>(&acc[j][k]);
                atomicAdd(op + qq + 4 * k, v.x + v.y);
            }
        }
        __syncwarp();  // buffers free before next unit overwrites
    }
}

// ---------------------------------------------------------------------------
extern "C" void kernel_launch(void* const* d_in, const int* in_sizes, int n_in,
                              void* d_out, int out_size) {
    const float* hidden = (const float*)d_in[0];
    const float* slot = (const float*)d_in[1];
    const int* labels = (const int*)d_in[2];
    const int* pB = (n_in > 3) ? (const int*)d_in[3] : nullptr;
    const int* pI = (n_in > 4) ? (const int*)d_in[4] : nullptr;
    const int* pMS = (n_in > 5) ? (const int*)d_in[5] : nullptr;
    float* out = (float*)d_out;

    static bool attr_set = false;
    if (!attr_set) {
        cudaFuncSetAttribute(proj_kernel, cudaFuncAttributeMaxDynamicSharedMemorySize,
                             SMEM_TOTAL);
        attr_set = true;
    }

    seg_zero_kernel<<<256, 256>>>(labels, pB, pI, pMS, out, out_size);
    proj_kernel<<<GRID_X, 256, SMEM_TOTAL>>>(hidden, slot, pMS, out);
}